// round 8
// baseline (speedup 1.0000x reference)
#include <cuda_runtime.h>
#include <math.h>

#define NN 50000
#define EE 800000
#define ETOT (EE + NN)      // edges + self loops
#define FF 128              // HEADS*HID = F_IN
#define HH 4
#define NC 8

typedef unsigned long long ull;

// ---- scratch (device globals; no allocation allowed) ----
__device__ __align__(16) float g_ht[(size_t)NN * FF];   // transformed features
__device__ __align__(16) float g_feat[(size_t)NN * FF]; // layer-0 output
__device__ __align__(16) float g_h2[NN * NC];           // layer-2 transformed
__device__ __align__(16) float g_as[NN * HH];
__device__ __align__(16) float g_ad[NN * HH];
__device__ __align__(16) float g_as2[NN];
__device__ __align__(16) float g_ad2[NN];
__device__ int g_srcp[ETOT];        // src per edge, sorted by dst (CSR)
__device__ int g_rowptr[NN + 1];    // CSR row pointers (by dst)
__device__ int g_deg[NN];
__device__ int g_ofs[NN];           // scatter cursors

// ---- packed f32x2 helpers (Blackwell FFMA2) ----
__device__ __forceinline__ ull fma2(ull a, ull b, ull c) {
    ull d;
    asm("fma.rn.f32x2 %0, %1, %2, %3;" : "=l"(d) : "l"(a), "l"(b), "l"(c));
    return d;
}
__device__ __forceinline__ ull pk2(float v) {
    ull d;
    asm("mov.b64 %0, {%1, %1};" : "=l"(d) : "f"(v));
    return d;
}
__device__ __forceinline__ float2 up2(ull a) {
    float2 r;
    asm("mov.b64 {%0, %1}, %2;" : "=f"(r.x), "=f"(r.y) : "l"(a));
    return r;
}

// ================= CSR construction =================
__global__ void k_deg(const int* __restrict__ ei) {
    int e = blockIdx.x * blockDim.x + threadIdx.x;
    if (e >= ETOT) return;
    int dst = (e < EE) ? ei[EE + e] : e - EE;
    atomicAdd(&g_deg[dst], 1);
}

// single-block scan, 4 elements/thread, chunked with carry
__global__ void k_scan() {
    __shared__ int wsum[32];
    __shared__ int carryS;
    int tid = threadIdx.x, lane = tid & 31, wid = tid >> 5;
    if (tid == 0) { carryS = 0; g_rowptr[0] = 0; }
    __syncthreads();
    for (int base = 0; base < NN; base += 4096) {
        int i0 = base + tid * 4;
        int d0 = (i0 + 0 < NN) ? g_deg[i0 + 0] : 0;
        int d1 = (i0 + 1 < NN) ? g_deg[i0 + 1] : 0;
        int d2 = (i0 + 2 < NN) ? g_deg[i0 + 2] : 0;
        int d3 = (i0 + 3 < NN) ? g_deg[i0 + 3] : 0;
        int v = d0 + d1 + d2 + d3;
        int x = v;
#pragma unroll
        for (int off = 1; off < 32; off <<= 1) {
            int t = __shfl_up_sync(0xffffffffu, x, off);
            if (lane >= off) x += t;
        }
        if (lane == 31) wsum[wid] = x;
        __syncthreads();
        if (wid == 0) {
            int w = wsum[lane];
#pragma unroll
            for (int off = 1; off < 32; off <<= 1) {
                int t = __shfl_up_sync(0xffffffffu, w, off);
                if (lane >= off) w += t;
            }
            wsum[lane] = w;
        }
        __syncthreads();
        int inc = x + (wid > 0 ? wsum[wid - 1] : 0);
        int carry = carryS;
        __syncthreads();
        int excl = carry + inc - v;
        int p0 = excl + d0, p1 = p0 + d1, p2 = p1 + d2, p3 = p2 + d3;
        if (i0 + 0 < NN) { g_rowptr[i0 + 1] = p0; g_ofs[i0 + 0] = excl; }
        if (i0 + 1 < NN) { g_rowptr[i0 + 2] = p1; g_ofs[i0 + 1] = p0; }
        if (i0 + 2 < NN) { g_rowptr[i0 + 3] = p2; g_ofs[i0 + 2] = p1; }
        if (i0 + 3 < NN) { g_rowptr[i0 + 4] = p3; g_ofs[i0 + 3] = p2; }
        if (tid == 1023) carryS = carry + inc;
        __syncthreads();
    }
}

__global__ void k_scatter(const int* __restrict__ ei) {
    int e = blockIdx.x * blockDim.x + threadIdx.x;
    if (e >= ETOT) return;
    int src, dst;
    if (e < EE) { src = ei[e]; dst = ei[EE + e]; } else { src = dst = e - EE; }
    int pos = atomicAdd(&g_ofs[dst], 1);
    g_srcp[pos] = src;
}

// ======== fused GEMM (128->128) + attention coefficients ========
// 128 thr = 4 warps, 32 nodes/block, 8 nodes/warp as 4 f32x2-packed PAIRS.
// x transposed in smem: node-pair input is one broadcast LDS.64.
__global__ __launch_bounds__(128) void k_gemm_attn(const float* __restrict__ X,
                                                   const float* __restrict__ W,
                                                   const float* __restrict__ as_,
                                                   const float* __restrict__ ad_) {
    __shared__ __align__(16) float xsT[FF][32];   // [k][node_local], 16KB
    int warp = threadIdx.x >> 5, lane = threadIdx.x & 31;
    int nb = blockIdx.x * 32;
    const float4* X4 = (const float4*)X;
    for (int i = threadIdx.x; i < 1024; i += 128) {
        int k4 = i >> 5, node = i & 31;     // warp covers one node's 32 k4? no: k4 fixed per warp-slice, node=lane
        int gn = nb + node;
        float4 xv = (gn < NN) ? X4[(size_t)gn * 32 + k4]
                              : make_float4(0.f, 0.f, 0.f, 0.f);
        xsT[k4 * 4 + 0][node] = xv.x;
        xsT[k4 * 4 + 1][node] = xv.y;
        xsT[k4 * 4 + 2][node] = xv.z;
        xsT[k4 * 4 + 3][node] = xv.w;
    }
    __syncthreads();
    ull acc[4][4];   // [pair][col]
#pragma unroll
    for (int p = 0; p < 4; p++)
#pragma unroll
        for (int c = 0; c < 4; c++) acc[p][c] = 0ull;
    int n0 = warp * 8;
    const float4* W4 = (const float4*)W;
#pragma unroll 2
    for (int k = 0; k < FF; k++) {
        float4 w = W4[(size_t)k * 32 + lane];       // cols 4lane..4lane+3
        ull w0 = pk2(w.x), w1 = pk2(w.y), w2 = pk2(w.z), w3 = pk2(w.w);
        const ull* xrow = (const ull*)&xsT[k][n0];  // 4 node-pairs, broadcast
#pragma unroll
        for (int p = 0; p < 4; p++) {
            ull xp = xrow[p];
            acc[p][0] = fma2(w0, xp, acc[p][0]);
            acc[p][1] = fma2(w1, xp, acc[p][1]);
            acc[p][2] = fma2(w2, xp, acc[p][2]);
            acc[p][3] = fma2(w3, xp, acc[p][3]);
        }
    }
    float4 as4 = ((const float4*)as_)[lane];
    float4 ad4 = ((const float4*)ad_)[lane];
    float4* O4 = (float4*)g_ht;
#pragma unroll
    for (int p = 0; p < 4; p++) {
        float2 c0 = up2(acc[p][0]), c1 = up2(acc[p][1]);
        float2 c2 = up2(acc[p][2]), c3 = up2(acc[p][3]);
#pragma unroll
        for (int half = 0; half < 2; half++) {
            int node = nb + n0 + 2 * p + half;
            float4 a = half == 0 ? make_float4(c0.x, c1.x, c2.x, c3.x)
                                 : make_float4(c0.y, c1.y, c2.y, c3.y);
            if (node < NN) {
                O4[(size_t)node * 32 + lane] = a;
                float ps = a.x * as4.x + a.y * as4.y + a.z * as4.z + a.w * as4.w;
                float pd = a.x * ad4.x + a.y * ad4.y + a.z * ad4.z + a.w * ad4.w;
#pragma unroll
                for (int off = 1; off < 8; off <<= 1) {
                    ps += __shfl_xor_sync(0xffffffffu, ps, off);
                    pd += __shfl_xor_sync(0xffffffffu, pd, off);
                }
                if ((lane & 7) == 0) {
                    int h = lane >> 3;
                    g_as[node * HH + h] = ps;
                    g_ad[node * HH + h] = pd;
                }
            }
        }
    }
}

// ======== CSR aggregation (warp per dst node) + bias + BN + ELU ========
// optionally fused layer-2 GEMM (128->8) + layer-2 attn coefficients
template <bool FUSE_L2>
__global__ __launch_bounds__(256) void k_agg4(const float* __restrict__ b,
                                              const float* __restrict__ g,
                                              const float* __restrict__ bb,
                                              const float* __restrict__ rm,
                                              const float* __restrict__ rv,
                                              const float* __restrict__ W2,
                                              const float* __restrict__ as2,
                                              const float* __restrict__ ad2) {
    __shared__ float4 s_ex[8][32];
    __shared__ int s_src[8][32];
    __shared__ float sW2t[NC][FF];
    int wid = threadIdx.x >> 5, lane = threadIdx.x & 31;
    if (FUSE_L2) {
        for (int i = threadIdx.x; i < FF * NC; i += 256) {
            int k = i >> 3, m = i & 7;
            sW2t[m][k] = W2[i];
        }
        __syncthreads();
    }
    int node = blockIdx.x * 8 + wid;
    int start = g_rowptr[node], end = g_rowptr[node + 1];
    float4 ad4 = ((const float4*)g_ad)[node];
    int hh = lane >> 3;
    float4 acc = make_float4(0.f, 0.f, 0.f, 0.f);
    float4 den = make_float4(0.f, 0.f, 0.f, 0.f);
    const float4* ht4 = (const float4*)g_ht;
    for (int base = start; base < end; base += 32) {
        int k = base + lane;
        float4 ex = make_float4(0.f, 0.f, 0.f, 0.f);
        int src = 0;
        if (k < end) {
            src = g_srcp[k];
            float4 a = ((const float4*)g_as)[src];
            float4 v;
            v.x = a.x + ad4.x; v.y = a.y + ad4.y; v.z = a.z + ad4.z; v.w = a.w + ad4.w;
            v.x = v.x > 0.f ? v.x : 0.2f * v.x;
            v.y = v.y > 0.f ? v.y : 0.2f * v.y;
            v.z = v.z > 0.f ? v.z : 0.2f * v.z;
            v.w = v.w > 0.f ? v.w : 0.2f * v.w;
            ex.x = __expf(v.x); ex.y = __expf(v.y); ex.z = __expf(v.z); ex.w = __expf(v.w);
            den.x += ex.x; den.y += ex.y; den.z += ex.z; den.w += ex.w;
        }
        s_src[wid][lane] = src;
        s_ex[wid][lane] = ex;
        __syncwarp();
        int cnt = min(32, end - base);
#pragma unroll 8
        for (int j = 0; j < cnt; j++) {
            int sj = s_src[wid][j];
            float al = ((const float*)&s_ex[wid][j])[hh];
            float4 hv = ht4[(size_t)sj * 32 + lane];
            acc.x += al * hv.x; acc.y += al * hv.y;
            acc.z += al * hv.z; acc.w += al * hv.w;
        }
        __syncwarp();
    }
#pragma unroll
    for (int off = 16; off; off >>= 1) {
        den.x += __shfl_xor_sync(0xffffffffu, den.x, off);
        den.y += __shfl_xor_sync(0xffffffffu, den.y, off);
        den.z += __shfl_xor_sync(0xffffffffu, den.z, off);
        den.w += __shfl_xor_sync(0xffffffffu, den.w, off);
    }
    float d = hh == 0 ? den.x : hh == 1 ? den.y : hh == 2 ? den.z : den.w;
    float inv = 1.f / (d + 1e-16f);
    acc.x *= inv; acc.y *= inv; acc.z *= inv; acc.w *= inv;
    // bias + BN(eval) + ELU epilogue
    float4 B = ((const float4*)b)[lane],  G = ((const float4*)g)[lane];
    float4 BB = ((const float4*)bb)[lane], RM = ((const float4*)rm)[lane];
    float4 RV = ((const float4*)rv)[lane];
    float4 v;
    v.x = (acc.x + B.x - RM.x) * rsqrtf(RV.x + 1e-5f) * G.x + BB.x;
    v.y = (acc.y + B.y - RM.y) * rsqrtf(RV.y + 1e-5f) * G.y + BB.y;
    v.z = (acc.z + B.z - RM.z) * rsqrtf(RV.z + 1e-5f) * G.z + BB.z;
    v.w = (acc.w + B.w - RM.w) * rsqrtf(RV.w + 1e-5f) * G.w + BB.w;
    v.x = v.x > 0.f ? v.x : __expf(v.x) - 1.f;
    v.y = v.y > 0.f ? v.y : __expf(v.y) - 1.f;
    v.z = v.z > 0.f ? v.z : __expf(v.z) - 1.f;
    v.w = v.w > 0.f ? v.w : __expf(v.w) - 1.f;
    if (!FUSE_L2) {
        ((float4*)g_feat)[(size_t)node * 32 + lane] = v;
    } else {
        // layer-2 GEMM: h2[m] = sum_c v[c] * W2[c][m], warp-reduce over lanes
        float h[NC];
#pragma unroll
        for (int m = 0; m < NC; m++) {
            float4 w = ((const float4*)(sW2t[m]))[lane];
            float p = v.x * w.x + v.y * w.y + v.z * w.z + v.w * w.w;
#pragma unroll
            for (int off = 16; off; off >>= 1)
                p += __shfl_xor_sync(0xffffffffu, p, off);
            h[m] = p;
        }
        if (lane == 0) {
            float ps = 0.f, pd = 0.f;
#pragma unroll
            for (int m = 0; m < NC; m++) {
                g_h2[node * NC + m] = h[m];
                ps += h[m] * as2[m];
                pd += h[m] * ad2[m];
            }
            g_as2[node] = ps;
            g_ad2[node] = pd;
        }
    }
}

// ======== layer 2 CSR aggregation (single pass) + bias + log_softmax ========
__global__ __launch_bounds__(256) void k_agg1_final(const float* __restrict__ b2,
                                                    float* __restrict__ out) {
    int wid = threadIdx.x >> 5, lane = threadIdx.x & 31;
    int node = blockIdx.x * 8 + wid;
    int start = g_rowptr[node], end = g_rowptr[node + 1];
    float adv = g_ad2[node];
    float den = 0.f;
    float4 a0 = make_float4(0.f, 0.f, 0.f, 0.f), a1 = a0;
    const float4* h2 = (const float4*)g_h2;
    for (int k = start + lane; k < end; k += 32) {
        int src = g_srcp[k];
        float v = g_as2[src] + adv;
        v = v > 0.f ? v : 0.2f * v;
        float ex = __expf(v);
        den += ex;
        float4 v0 = h2[(size_t)src * 2];
        float4 v1 = h2[(size_t)src * 2 + 1];
        a0.x += ex * v0.x; a0.y += ex * v0.y; a0.z += ex * v0.z; a0.w += ex * v0.w;
        a1.x += ex * v1.x; a1.y += ex * v1.y; a1.z += ex * v1.z; a1.w += ex * v1.w;
    }
#pragma unroll
    for (int off = 16; off; off >>= 1) {
        den  += __shfl_xor_sync(0xffffffffu, den, off);
        a0.x += __shfl_xor_sync(0xffffffffu, a0.x, off);
        a0.y += __shfl_xor_sync(0xffffffffu, a0.y, off);
        a0.z += __shfl_xor_sync(0xffffffffu, a0.z, off);
        a0.w += __shfl_xor_sync(0xffffffffu, a0.w, off);
        a1.x += __shfl_xor_sync(0xffffffffu, a1.x, off);
        a1.y += __shfl_xor_sync(0xffffffffu, a1.y, off);
        a1.z += __shfl_xor_sync(0xffffffffu, a1.z, off);
        a1.w += __shfl_xor_sync(0xffffffffu, a1.w, off);
    }
    if (lane == 0) {
        float inv = 1.f / (den + 1e-16f);
        float v[NC] = { a0.x * inv + b2[0], a0.y * inv + b2[1],
                        a0.z * inv + b2[2], a0.w * inv + b2[3],
                        a1.x * inv + b2[4], a1.y * inv + b2[5],
                        a1.z * inv + b2[6], a1.w * inv + b2[7] };
        float mx = -INFINITY;
#pragma unroll
        for (int j = 0; j < NC; j++) mx = fmaxf(mx, v[j]);
        float s = 0.f;
#pragma unroll
        for (int j = 0; j < NC; j++) s += __expf(v[j] - mx);
        float ls = __logf(s) + mx;
#pragma unroll
        for (int j = 0; j < NC; j++) out[node * NC + j] = v[j] - ls;
    }
}

extern "C" void kernel_launch(void* const* d_in, const int* in_sizes, int n_in,
                              void* d_out, int out_size) {
    const float* x   = (const float*)d_in[0];
    const int*   ei  = (const int*)d_in[1];
    const float* W0  = (const float*)d_in[2];
    const float* as0 = (const float*)d_in[3];
    const float* ad0 = (const float*)d_in[4];
    const float* b0  = (const float*)d_in[5];
    const float* g0  = (const float*)d_in[6];
    const float* bb0 = (const float*)d_in[7];
    const float* rm0 = (const float*)d_in[8];
    const float* rv0 = (const float*)d_in[9];
    const float* W1  = (const float*)d_in[10];
    const float* as1 = (const float*)d_in[11];
    const float* ad1 = (const float*)d_in[12];
    const float* b1  = (const float*)d_in[13];
    const float* g1  = (const float*)d_in[14];
    const float* bb1 = (const float*)d_in[15];
    const float* rm1 = (const float*)d_in[16];
    const float* rv1 = (const float*)d_in[17];
    const float* W2  = (const float*)d_in[18];
    const float* as2 = (const float*)d_in[19];
    const float* ad2 = (const float*)d_in[20];
    const float* b2  = (const float*)d_in[21];
    float* out = (float*)d_out;

    float* feat_ptr = nullptr;
    cudaGetSymbolAddress((void**)&feat_ptr, g_feat);
    int* deg_ptr = nullptr;
    cudaGetSymbolAddress((void**)&deg_ptr, g_deg);

    const int TB = 256;

    // ---- CSR build ----
    cudaMemsetAsync(deg_ptr, 0, NN * sizeof(int));
    k_deg<<<(ETOT + TB - 1) / TB, TB>>>(ei);
    k_scan<<<1, 1024>>>();
    k_scatter<<<(ETOT + TB - 1) / TB, TB>>>(ei);

    // ======== layer 0 ========
    k_gemm_attn<<<(NN + 31) / 32, 128>>>(x, W0, as0, ad0);
    k_agg4<false><<<NN / 8, TB>>>(b0, g0, bb0, rm0, rv0, nullptr, nullptr, nullptr);

    // ======== layer 1 (+ fused layer-2 GEMM/attn) ========
    k_gemm_attn<<<(NN + 31) / 32, 128>>>(feat_ptr, W1, as1, ad1);
    k_agg4<true><<<NN / 8, TB>>>(b1, g1, bb1, rm1, rv1, W2, as2, ad2);

    // ======== layer 2 aggregation + log_softmax ========
    k_agg1_final<<<NN / 8, TB>>>(b2, out);
}

// round 9
// speedup vs baseline: 1.1166x; 1.1166x over previous
#include <cuda_runtime.h>
#include <math.h>

#define NN 50000
#define EE 800000
#define ETOT (EE + NN)      // edges + self loops
#define FF 128              // HEADS*HID = F_IN
#define HH 4
#define NC 8

typedef unsigned long long ull;

// ---- scratch (device globals; no allocation allowed) ----
__device__ __align__(16) float g_ht[(size_t)NN * FF];   // transformed features
__device__ __align__(16) float g_feat[(size_t)NN * FF]; // layer-0 output
__device__ __align__(16) float g_h2[NN * NC];           // layer-2 transformed
__device__ __align__(16) float g_as[NN * HH];
__device__ __align__(16) float g_ad[NN * HH];
__device__ __align__(16) float g_as2[NN];
__device__ __align__(16) float g_ad2[NN];
__device__ int g_srcp[ETOT];        // src per edge, sorted by dst (CSR)
__device__ int g_rowptr[NN + 1];    // CSR row pointers (by dst)
__device__ int g_deg[NN];
__device__ int g_ofs[NN];           // scatter cursors

// ---- packed f32x2 helpers (Blackwell FFMA2) ----
__device__ __forceinline__ ull fma2(ull a, ull b, ull c) {
    ull d;
    asm("fma.rn.f32x2 %0, %1, %2, %3;" : "=l"(d) : "l"(a), "l"(b), "l"(c));
    return d;
}
__device__ __forceinline__ ull pk2(float v) {
    ull d;
    asm("mov.b64 %0, {%1, %1};" : "=l"(d) : "f"(v));
    return d;
}
__device__ __forceinline__ float2 up2(ull a) {
    float2 r;
    asm("mov.b64 {%0, %1}, %2;" : "=f"(r.x), "=f"(r.y) : "l"(a));
    return r;
}

// ================= CSR construction =================
__global__ void k_deg(const int* __restrict__ ei) {
    int e = blockIdx.x * blockDim.x + threadIdx.x;
    if (e >= ETOT) return;
    int dst = (e < EE) ? ei[EE + e] : e - EE;
    atomicAdd(&g_deg[dst], 1);
}

// single-block scan, 4 elements/thread, chunked with carry
__global__ void k_scan() {
    __shared__ int wsum[32];
    __shared__ int carryS;
    int tid = threadIdx.x, lane = tid & 31, wid = tid >> 5;
    if (tid == 0) { carryS = 0; g_rowptr[0] = 0; }
    __syncthreads();
    for (int base = 0; base < NN; base += 4096) {
        int i0 = base + tid * 4;
        int d0 = (i0 + 0 < NN) ? g_deg[i0 + 0] : 0;
        int d1 = (i0 + 1 < NN) ? g_deg[i0 + 1] : 0;
        int d2 = (i0 + 2 < NN) ? g_deg[i0 + 2] : 0;
        int d3 = (i0 + 3 < NN) ? g_deg[i0 + 3] : 0;
        int v = d0 + d1 + d2 + d3;
        int x = v;
#pragma unroll
        for (int off = 1; off < 32; off <<= 1) {
            int t = __shfl_up_sync(0xffffffffu, x, off);
            if (lane >= off) x += t;
        }
        if (lane == 31) wsum[wid] = x;
        __syncthreads();
        if (wid == 0) {
            int w = wsum[lane];
#pragma unroll
            for (int off = 1; off < 32; off <<= 1) {
                int t = __shfl_up_sync(0xffffffffu, w, off);
                if (lane >= off) w += t;
            }
            wsum[lane] = w;
        }
        __syncthreads();
        int inc = x + (wid > 0 ? wsum[wid - 1] : 0);
        int carry = carryS;
        __syncthreads();
        int excl = carry + inc - v;
        int p0 = excl + d0, p1 = p0 + d1, p2 = p1 + d2, p3 = p2 + d3;
        if (i0 + 0 < NN) { g_rowptr[i0 + 1] = p0; g_ofs[i0 + 0] = excl; }
        if (i0 + 1 < NN) { g_rowptr[i0 + 2] = p1; g_ofs[i0 + 1] = p0; }
        if (i0 + 2 < NN) { g_rowptr[i0 + 3] = p2; g_ofs[i0 + 2] = p1; }
        if (i0 + 3 < NN) { g_rowptr[i0 + 4] = p3; g_ofs[i0 + 3] = p2; }
        if (tid == 1023) carryS = carry + inc;
        __syncthreads();
    }
}

__global__ void k_scatter(const int* __restrict__ ei) {
    int e = blockIdx.x * blockDim.x + threadIdx.x;
    if (e >= ETOT) return;
    int src, dst;
    if (e < EE) { src = ei[e]; dst = ei[EE + e]; } else { src = dst = e - EE; }
    int pos = atomicAdd(&g_ofs[dst], 1);
    g_srcp[pos] = src;
}

// ======== fused GEMM (128->128, f32x2 packed) + attention coefficients ========
// block = 128 thr (4 warps), 16 nodes/block, 4 nodes/warp, 4 cols (2xf32x2)/lane
__global__ __launch_bounds__(128) void k_gemm_attn(const float* __restrict__ X,
                                                   const float* __restrict__ W,
                                                   const float* __restrict__ as_,
                                                   const float* __restrict__ ad_) {
    __shared__ __align__(16) float xs[16 * FF];
    int warp = threadIdx.x >> 5, lane = threadIdx.x & 31;
    int nb = blockIdx.x * 16;
    const float4* X4 = (const float4*)(X + (size_t)nb * FF);
    float4* xs4 = (float4*)xs;
    for (int i = threadIdx.x; i < 16 * 32; i += 128) xs4[i] = X4[i];
    __syncthreads();
    ull acc[4][2];
#pragma unroll
    for (int j = 0; j < 4; j++) { acc[j][0] = 0ull; acc[j][1] = 0ull; }
    const ulonglong2* W2 = (const ulonglong2*)W;
    int n0 = warp * 4;
#pragma unroll 4
    for (int k4 = 0; k4 < 32; k4++) {
        float4 xv[4];
#pragma unroll
        for (int j = 0; j < 4; j++) xv[j] = xs4[(n0 + j) * 32 + k4];
#pragma unroll
        for (int c = 0; c < 4; c++) {
            ulonglong2 w = W2[(size_t)(k4 * 4 + c) * 32 + lane];
#pragma unroll
            for (int j = 0; j < 4; j++) {
                float xj = (c == 0) ? xv[j].x : (c == 1) ? xv[j].y : (c == 2) ? xv[j].z : xv[j].w;
                ull xx = pk2(xj);
                acc[j][0] = fma2(w.x, xx, acc[j][0]);
                acc[j][1] = fma2(w.y, xx, acc[j][1]);
            }
        }
    }
    float4* O4 = (float4*)g_ht;
    float4 as4 = ((const float4*)as_)[lane];
    float4 ad4 = ((const float4*)ad_)[lane];
#pragma unroll
    for (int j = 0; j < 4; j++) {
        float2 lo = up2(acc[j][0]), hi = up2(acc[j][1]);
        float4 a = make_float4(lo.x, lo.y, hi.x, hi.y);
        O4[(size_t)(nb + n0 + j) * 32 + lane] = a;
        float ps = a.x * as4.x + a.y * as4.y + a.z * as4.z + a.w * as4.w;
        float pd = a.x * ad4.x + a.y * ad4.y + a.z * ad4.z + a.w * ad4.w;
#pragma unroll
        for (int off = 1; off < 8; off <<= 1) {
            ps += __shfl_xor_sync(0xffffffffu, ps, off);
            pd += __shfl_xor_sync(0xffffffffu, pd, off);
        }
        if ((lane & 7) == 0) {
            int h = lane >> 3;
            g_as[(nb + n0 + j) * HH + h] = ps;
            g_ad[(nb + n0 + j) * HH + h] = pd;
        }
    }
}

// ======== CSR aggregation (warp per dst node) + bias + BN + ELU ========
// optionally fused layer-2 GEMM (128->8) + layer-2 attn coefficients
template <bool FUSE_L2>
__global__ __launch_bounds__(256) void k_agg4(const float* __restrict__ b,
                                              const float* __restrict__ g,
                                              const float* __restrict__ bb,
                                              const float* __restrict__ rm,
                                              const float* __restrict__ rv,
                                              const float* __restrict__ W2,
                                              const float* __restrict__ as2,
                                              const float* __restrict__ ad2) {
    __shared__ float4 s_ex[8][32];
    __shared__ int s_src[8][32];
    __shared__ float sW2t[NC][FF];
    int wid = threadIdx.x >> 5, lane = threadIdx.x & 31;
    if (FUSE_L2) {
        for (int i = threadIdx.x; i < FF * NC; i += 256) {
            int k = i >> 3, m = i & 7;
            sW2t[m][k] = W2[i];
        }
        __syncthreads();
    }
    int node = blockIdx.x * 8 + wid;
    int start = g_rowptr[node], end = g_rowptr[node + 1];
    float4 ad4 = ((const float4*)g_ad)[node];
    int hh = lane >> 3;
    float4 acc = make_float4(0.f, 0.f, 0.f, 0.f);
    float4 den = make_float4(0.f, 0.f, 0.f, 0.f);
    const float4* ht4 = (const float4*)g_ht;
    for (int base = start; base < end; base += 32) {
        int k = base + lane;
        float4 ex = make_float4(0.f, 0.f, 0.f, 0.f);
        int src = 0;
        if (k < end) {
            src = g_srcp[k];
            float4 a = ((const float4*)g_as)[src];
            float4 v;
            v.x = a.x + ad4.x; v.y = a.y + ad4.y; v.z = a.z + ad4.z; v.w = a.w + ad4.w;
            v.x = v.x > 0.f ? v.x : 0.2f * v.x;
            v.y = v.y > 0.f ? v.y : 0.2f * v.y;
            v.z = v.z > 0.f ? v.z : 0.2f * v.z;
            v.w = v.w > 0.f ? v.w : 0.2f * v.w;
            ex.x = __expf(v.x); ex.y = __expf(v.y); ex.z = __expf(v.z); ex.w = __expf(v.w);
            den.x += ex.x; den.y += ex.y; den.z += ex.z; den.w += ex.w;
        }
        s_src[wid][lane] = src;
        s_ex[wid][lane] = ex;
        __syncwarp();
        int cnt = min(32, end - base);
#pragma unroll 8
        for (int j = 0; j < cnt; j++) {
            int sj = s_src[wid][j];
            float al = ((const float*)&s_ex[wid][j])[hh];
            float4 hv = ht4[(size_t)sj * 32 + lane];
            acc.x += al * hv.x; acc.y += al * hv.y;
            acc.z += al * hv.z; acc.w += al * hv.w;
        }
        __syncwarp();
    }
#pragma unroll
    for (int off = 16; off; off >>= 1) {
        den.x += __shfl_xor_sync(0xffffffffu, den.x, off);
        den.y += __shfl_xor_sync(0xffffffffu, den.y, off);
        den.z += __shfl_xor_sync(0xffffffffu, den.z, off);
        den.w += __shfl_xor_sync(0xffffffffu, den.w, off);
    }
    float d = hh == 0 ? den.x : hh == 1 ? den.y : hh == 2 ? den.z : den.w;
    float inv = 1.f / (d + 1e-16f);
    acc.x *= inv; acc.y *= inv; acc.z *= inv; acc.w *= inv;
    // bias + BN(eval) + ELU epilogue
    float4 B = ((const float4*)b)[lane],  G = ((const float4*)g)[lane];
    float4 BB = ((const float4*)bb)[lane], RM = ((const float4*)rm)[lane];
    float4 RV = ((const float4*)rv)[lane];
    float4 v;
    v.x = (acc.x + B.x - RM.x) * rsqrtf(RV.x + 1e-5f) * G.x + BB.x;
    v.y = (acc.y + B.y - RM.y) * rsqrtf(RV.y + 1e-5f) * G.y + BB.y;
    v.z = (acc.z + B.z - RM.z) * rsqrtf(RV.z + 1e-5f) * G.z + BB.z;
    v.w = (acc.w + B.w - RM.w) * rsqrtf(RV.w + 1e-5f) * G.w + BB.w;
    v.x = v.x > 0.f ? v.x : __expf(v.x) - 1.f;
    v.y = v.y > 0.f ? v.y : __expf(v.y) - 1.f;
    v.z = v.z > 0.f ? v.z : __expf(v.z) - 1.f;
    v.w = v.w > 0.f ? v.w : __expf(v.w) - 1.f;
    if (!FUSE_L2) {
        ((float4*)g_feat)[(size_t)node * 32 + lane] = v;
    } else {
        // layer-2 GEMM: h2[m] = sum_c v[c] * W2[c][m], warp-reduce over lanes
        float h[NC];
#pragma unroll
        for (int m = 0; m < NC; m++) {
            float4 w = ((const float4*)(sW2t[m]))[lane];
            float p = v.x * w.x + v.y * w.y + v.z * w.z + v.w * w.w;
#pragma unroll
            for (int off = 16; off; off >>= 1)
                p += __shfl_xor_sync(0xffffffffu, p, off);
            h[m] = p;
        }
        if (lane == 0) {
            float ps = 0.f, pd = 0.f;
#pragma unroll
            for (int m = 0; m < NC; m++) {
                g_h2[node * NC + m] = h[m];
                ps += h[m] * as2[m];
                pd += h[m] * ad2[m];
            }
            g_as2[node] = ps;
            g_ad2[node] = pd;
        }
    }
}

// ======== layer 2 CSR aggregation (single pass) + bias + log_softmax ========
__global__ __launch_bounds__(256) void k_agg1_final(const float* __restrict__ b2,
                                                    float* __restrict__ out) {
    int wid = threadIdx.x >> 5, lane = threadIdx.x & 31;
    int node = blockIdx.x * 8 + wid;
    int start = g_rowptr[node], end = g_rowptr[node + 1];
    float adv = g_ad2[node];
    float den = 0.f;
    float4 a0 = make_float4(0.f, 0.f, 0.f, 0.f), a1 = a0;
    const float4* h2 = (const float4*)g_h2;
    for (int k = start + lane; k < end; k += 32) {
        int src = g_srcp[k];
        float v = g_as2[src] + adv;
        v = v > 0.f ? v : 0.2f * v;
        float ex = __expf(v);
        den += ex;
        float4 v0 = h2[(size_t)src * 2];
        float4 v1 = h2[(size_t)src * 2 + 1];
        a0.x += ex * v0.x; a0.y += ex * v0.y; a0.z += ex * v0.z; a0.w += ex * v0.w;
        a1.x += ex * v1.x; a1.y += ex * v1.y; a1.z += ex * v1.z; a1.w += ex * v1.w;
    }
#pragma unroll
    for (int off = 16; off; off >>= 1) {
        den  += __shfl_xor_sync(0xffffffffu, den, off);
        a0.x += __shfl_xor_sync(0xffffffffu, a0.x, off);
        a0.y += __shfl_xor_sync(0xffffffffu, a0.y, off);
        a0.z += __shfl_xor_sync(0xffffffffu, a0.z, off);
        a0.w += __shfl_xor_sync(0xffffffffu, a0.w, off);
        a1.x += __shfl_xor_sync(0xffffffffu, a1.x, off);
        a1.y += __shfl_xor_sync(0xffffffffu, a1.y, off);
        a1.z += __shfl_xor_sync(0xffffffffu, a1.z, off);
        a1.w += __shfl_xor_sync(0xffffffffu, a1.w, off);
    }
    if (lane == 0) {
        float inv = 1.f / (den + 1e-16f);
        float v[NC] = { a0.x * inv + b2[0], a0.y * inv + b2[1],
                        a0.z * inv + b2[2], a0.w * inv + b2[3],
                        a1.x * inv + b2[4], a1.y * inv + b2[5],
                        a1.z * inv + b2[6], a1.w * inv + b2[7] };
        float mx = -INFINITY;
#pragma unroll
        for (int j = 0; j < NC; j++) mx = fmaxf(mx, v[j]);
        float s = 0.f;
#pragma unroll
        for (int j = 0; j < NC; j++) s += __expf(v[j] - mx);
        float ls = __logf(s) + mx;
#pragma unroll
        for (int j = 0; j < NC; j++) out[node * NC + j] = v[j] - ls;
    }
}

extern "C" void kernel_launch(void* const* d_in, const int* in_sizes, int n_in,
                              void* d_out, int out_size) {
    const float* x   = (const float*)d_in[0];
    const int*   ei  = (const int*)d_in[1];
    const float* W0  = (const float*)d_in[2];
    const float* as0 = (const float*)d_in[3];
    const float* ad0 = (const float*)d_in[4];
    const float* b0  = (const float*)d_in[5];
    const float* g0  = (const float*)d_in[6];
    const float* bb0 = (const float*)d_in[7];
    const float* rm0 = (const float*)d_in[8];
    const float* rv0 = (const float*)d_in[9];
    const float* W1  = (const float*)d_in[10];
    const float* as1 = (const float*)d_in[11];
    const float* ad1 = (const float*)d_in[12];
    const float* b1  = (const float*)d_in[13];
    const float* g1  = (const float*)d_in[14];
    const float* bb1 = (const float*)d_in[15];
    const float* rm1 = (const float*)d_in[16];
    const float* rv1 = (const float*)d_in[17];
    const float* W2  = (const float*)d_in[18];
    const float* as2 = (const float*)d_in[19];
    const float* ad2 = (const float*)d_in[20];
    const float* b2  = (const float*)d_in[21];
    float* out = (float*)d_out;

    float* feat_ptr = nullptr;
    cudaGetSymbolAddress((void**)&feat_ptr, g_feat);
    int* deg_ptr = nullptr;
    cudaGetSymbolAddress((void**)&deg_ptr, g_deg);

    // one-time side stream + events for fork-join inside graph capture
    static cudaStream_t s2 = nullptr;
    static cudaEvent_t evFork = nullptr, evJoin = nullptr;
    if (!s2) {
        cudaStreamCreateWithFlags(&s2, cudaStreamNonBlocking);
        cudaEventCreateWithFlags(&evFork, cudaEventDisableTiming);
        cudaEventCreateWithFlags(&evJoin, cudaEventDisableTiming);
    }

    const int TB = 256;

    // ---- fork: CSR build on s2, concurrent with layer-0 GEMM on stream 0 ----
    cudaEventRecord(evFork, 0);
    cudaStreamWaitEvent(s2, evFork, 0);

    cudaMemsetAsync(deg_ptr, 0, NN * sizeof(int), s2);
    k_deg<<<(ETOT + TB - 1) / TB, TB, 0, s2>>>(ei);
    k_scan<<<1, 1024, 0, s2>>>();
    k_scatter<<<(ETOT + TB - 1) / TB, TB, 0, s2>>>(ei);
    cudaEventRecord(evJoin, s2);

    // ======== layer 0 GEMM (independent of CSR) ========
    k_gemm_attn<<<NN / 16, 128>>>(x, W0, as0, ad0);

    // ---- join: aggregation needs both CSR and GEMM results ----
    cudaStreamWaitEvent(0, evJoin, 0);

    k_agg4<false><<<NN / 8, TB>>>(b0, g0, bb0, rm0, rv0, nullptr, nullptr, nullptr);

    // ======== layer 1 (+ fused layer-2 GEMM/attn) ========
    k_gemm_attn<<<NN / 16, 128>>>(feat_ptr, W1, as1, ad1);
    k_agg4<true><<<NN / 8, TB>>>(b1, g1, bb1, rm1, rv1, W2, as2, ad2);

    // ======== layer 2 aggregation + log_softmax ========
    k_agg1_final<<<NN / 8, TB>>>(b2, out);
}